// round 9
// baseline (speedup 1.0000x reference)
#include <cuda_runtime.h>
#include <math.h>

// ---------------- problem constants ----------------
#define Lq   4          // sequence length (B=1)
#define Cc   128        // channels
#define Ch   64         // hidden = C/2
#define Rr   8          // rank
#define Kk   36         // Lmax^2
#define HW   115200     // 240*480 pixels per plane
#define WFN  (Cc*Rr + Rr*Kk)   // 1312 hypernet output width
#define SEG  (HW/4)     // 28800 floats per mean segment

// ---------------- device scratch ----------------
__device__ float g_part[Lq * Cc * 4];       // partial plane sums
__device__ float g_h  [Lq * Ch];            // hidden activations
__device__ float g_gW1[Lq * Cc * Rr];       // gain[c]*W1[l,c,r]
__device__ float g_W2 [Lq * Rr * Kk];       // W2[l,r,k]

// ============================================================
// Kernel 1: partial sums of x planes. grid = 2048 (4 seg/plane),
// 256 threads, MLP=4 batched float4 loads.
// ============================================================
__global__ void mean_kernel(const float* __restrict__ x)
{
    const int bid   = blockIdx.x;
    const int plane = bid >> 2;
    const int seg   = bid & 3;
    const float4* __restrict__ p =
        (const float4*)(x + (size_t)plane * HW + (size_t)seg * SEG);
    const int n4 = SEG / 4;                       // 7200

    float s0 = 0.f, s1 = 0.f, s2 = 0.f, s3 = 0.f;
    int i = threadIdx.x;
    for (; i + 768 < n4; i += 1024) {
        float4 a = p[i];
        float4 b = p[i + 256];
        float4 c = p[i + 512];
        float4 d = p[i + 768];
        s0 += (a.x + a.y) + (a.z + a.w);
        s1 += (b.x + b.y) + (b.z + b.w);
        s2 += (c.x + c.y) + (c.z + c.w);
        s3 += (d.x + d.y) + (d.z + d.w);
    }
    for (; i < n4; i += 256) {
        float4 a = p[i];
        s0 += (a.x + a.y) + (a.z + a.w);
    }
    float s = (s0 + s1) + (s2 + s3);

    #pragma unroll
    for (int o = 16; o > 0; o >>= 1)
        s += __shfl_xor_sync(0xffffffffu, s, o);

    __shared__ float ws[8];
    const int lane = threadIdx.x & 31, wid = threadIdx.x >> 5;
    if (lane == 0) ws[wid] = s;
    __syncthreads();
    if (wid == 0) {
        s = (lane < 8) ? ws[lane] : 0.f;
        #pragma unroll
        for (int o = 4; o > 0; o >>= 1)
            s += __shfl_xor_sync(0xffffffffu, s, o);
        if (lane == 0)
            g_part[bid] = s;
    }
}

// ============================================================
// Kernel 2a: ctx reduce + layer 1 (h = silu(ctx@Wa+ba)).
// ============================================================
__global__ void hyperA_kernel(const float* __restrict__ Wa,
                              const float* __restrict__ ba)
{
    __shared__ float ctxs[Lq * Cc];
    const int tid = threadIdx.x;

    if (tid < Lq * Cc) {
        const float* gp = &g_part[tid * 4];
        ctxs[tid] = ((gp[0] + gp[1]) + (gp[2] + gp[3])) * (1.0f / (float)HW);
    }
    __syncthreads();

    if (tid < Lq * Ch) {
        const int l = tid >> 6;
        const int j = tid & 63;
        float acc = ba[j];
        const float* c = &ctxs[l * Cc];
        #pragma unroll 8
        for (int i = 0; i < Cc; i++)
            acc = fmaf(c[i], Wa[i * Ch + j], acc);
        g_h[tid] = acc / (1.0f + expf(-acc));
    }
}

// ============================================================
// Kernel 2b: layer 2 (wf = h@Wb+bb) -> gW1 / W2.  41 blocks.
// ============================================================
__global__ void __launch_bounds__(128)
hyperB_kernel(const float* __restrict__ Wb,
              const float* __restrict__ bb,
              const float* __restrict__ gain)
{
    __shared__ float hs[Lq * Ch];
    for (int i = threadIdx.x; i < Lq * Ch; i += 128) hs[i] = g_h[i];
    __syncthreads();

    const int idx = blockIdx.x * 128 + threadIdx.x;
    const int l   = idx / WFN;
    const int col = idx - l * WFN;

    float acc = bb[col];
    const float* h = &hs[l * Ch];
    #pragma unroll 8
    for (int j = 0; j < Ch; j++)
        acc = fmaf(h[j], Wb[j * WFN + col], acc);

    if (col < Cc * Rr) {
        const int c = col >> 3;
        g_gW1[l * (Cc * Rr) + col] = gain[c] * acc;
    } else {
        g_W2[l * (Rr * Kk) + (col - Cc * Rr)] = acc;
    }
}

// ============================================================
// Kernel 3: fused  z = W2 @ Y + out = x + gW1 @ z
// 256 threads, 2 px/thread (low regs -> ~40 warps/SM resident),
// channel loop unrolled x4 with front-batched loads (MLP=4).
// grid = (225, 4).
// ============================================================
__global__ void __launch_bounds__(256)
bias_kernel(const float* __restrict__ x,
            const float* __restrict__ Y,
            float*       __restrict__ out)
{
    const int l  = blockIdx.y;
    const int p0 = (blockIdx.x * 256 + threadIdx.x) * 2;

    __shared__ float sW2[Rr * Kk];
    __shared__ float sW1[Cc * Rr];

    for (int i = threadIdx.x; i < Rr * Kk; i += 256) sW2[i] = g_W2[l * Rr * Kk + i];
    for (int i = threadIdx.x; i < Cc * Rr; i += 256) sW1[i] = g_gW1[l * Cc * Rr + i];
    __syncthreads();

    // ---- z[r] for 2 pixels ----
    float2 z[Rr];
    #pragma unroll
    for (int r = 0; r < Rr; r++) z[r] = make_float2(0.f, 0.f);

    #pragma unroll
    for (int k = 0; k < Kk; k++) {
        const float2 y = *(const float2*)(Y + (size_t)k * HW + p0);
        #pragma unroll
        for (int r = 0; r < Rr; r++) {
            const float w = sW2[r * Kk + k];
            z[r].x = fmaf(w, y.x, z[r].x);
            z[r].y = fmaf(w, y.y, z[r].y);
        }
    }

    // ---- out = x + gW1 . z, 4 channels per iteration ----
    const float* xb = x   + (size_t)l * Cc * HW + p0;
    float*       ob = out + (size_t)l * Cc * HW + p0;

    #pragma unroll 2
    for (int c0 = 0; c0 < Cc; c0 += 4) {
        // front-batched loads (MLP_p1 = 4)
        float2 v0 = *(const float2*)(xb + (size_t)(c0 + 0) * HW);
        float2 v1 = *(const float2*)(xb + (size_t)(c0 + 1) * HW);
        float2 v2 = *(const float2*)(xb + (size_t)(c0 + 2) * HW);
        float2 v3 = *(const float2*)(xb + (size_t)(c0 + 3) * HW);

        #pragma unroll
        for (int r4 = 0; r4 < 2; r4++) {
            const float4 w0 = *(const float4*)&sW1[(c0 + 0) * Rr + 4 * r4];
            const float4 w1 = *(const float4*)&sW1[(c0 + 1) * Rr + 4 * r4];
            const float4 w2 = *(const float4*)&sW1[(c0 + 2) * Rr + 4 * r4];
            const float4 w3 = *(const float4*)&sW1[(c0 + 3) * Rr + 4 * r4];
            const int rb = 4 * r4;
            v0.x = fmaf(w0.x, z[rb+0].x, v0.x); v0.y = fmaf(w0.x, z[rb+0].y, v0.y);
            v0.x = fmaf(w0.y, z[rb+1].x, v0.x); v0.y = fmaf(w0.y, z[rb+1].y, v0.y);
            v0.x = fmaf(w0.z, z[rb+2].x, v0.x); v0.y = fmaf(w0.z, z[rb+2].y, v0.y);
            v0.x = fmaf(w0.w, z[rb+3].x, v0.x); v0.y = fmaf(w0.w, z[rb+3].y, v0.y);
            v1.x = fmaf(w1.x, z[rb+0].x, v1.x); v1.y = fmaf(w1.x, z[rb+0].y, v1.y);
            v1.x = fmaf(w1.y, z[rb+1].x, v1.x); v1.y = fmaf(w1.y, z[rb+1].y, v1.y);
            v1.x = fmaf(w1.z, z[rb+2].x, v1.x); v1.y = fmaf(w1.z, z[rb+2].y, v1.y);
            v1.x = fmaf(w1.w, z[rb+3].x, v1.x); v1.y = fmaf(w1.w, z[rb+3].y, v1.y);
            v2.x = fmaf(w2.x, z[rb+0].x, v2.x); v2.y = fmaf(w2.x, z[rb+0].y, v2.y);
            v2.x = fmaf(w2.y, z[rb+1].x, v2.x); v2.y = fmaf(w2.y, z[rb+1].y, v2.y);
            v2.x = fmaf(w2.z, z[rb+2].x, v2.x); v2.y = fmaf(w2.z, z[rb+2].y, v2.y);
            v2.x = fmaf(w2.w, z[rb+3].x, v2.x); v2.y = fmaf(w2.w, z[rb+3].y, v2.y);
            v3.x = fmaf(w3.x, z[rb+0].x, v3.x); v3.y = fmaf(w3.x, z[rb+0].y, v3.y);
            v3.x = fmaf(w3.y, z[rb+1].x, v3.x); v3.y = fmaf(w3.y, z[rb+1].y, v3.y);
            v3.x = fmaf(w3.z, z[rb+2].x, v3.x); v3.y = fmaf(w3.z, z[rb+2].y, v3.y);
            v3.x = fmaf(w3.w, z[rb+3].x, v3.x); v3.y = fmaf(w3.w, z[rb+3].y, v3.y);
        }

        *(float2*)(ob + (size_t)(c0 + 0) * HW) = v0;
        *(float2*)(ob + (size_t)(c0 + 1) * HW) = v1;
        *(float2*)(ob + (size_t)(c0 + 2) * HW) = v2;
        *(float2*)(ob + (size_t)(c0 + 3) * HW) = v3;
    }
}

// ============================================================
extern "C" void kernel_launch(void* const* d_in, const int* in_sizes, int n_in,
                              void* d_out, int out_size)
{
    const float* x    = (const float*)d_in[0];
    const float* Wa   = (const float*)d_in[1];
    const float* ba   = (const float*)d_in[2];
    const float* Wb   = (const float*)d_in[3];
    const float* bb   = (const float*)d_in[4];
    const float* gain = (const float*)d_in[5];
    const float* Y    = (const float*)d_in[6];
    float* out        = (float*)d_out;

    mean_kernel<<<Lq * Cc * 4, 256>>>(x);
    hyperA_kernel<<<1, 512>>>(Wa, ba);
    hyperB_kernel<<<41, 128>>>(Wb, bb, gain);
    bias_kernel<<<dim3(225, Lq), 256>>>(x, Y, out);
}

// round 11
// speedup vs baseline: 1.1080x; 1.1080x over previous
#include <cuda_runtime.h>
#include <math.h>

// ---------------- problem constants ----------------
#define Lq   4          // sequence length (B=1)
#define Cc   128        // channels
#define Ch   64         // hidden = C/2
#define Rr   8          // rank
#define Kk   36         // Lmax^2
#define HW   115200     // 240*480 pixels per plane
#define WFN  (Cc*Rr + Rr*Kk)   // 1312 hypernet output width
#define SEG  (HW/4)     // 28800 floats per mean segment

// ---------------- device scratch ----------------
__device__ float g_part[Lq * Cc * 4];       // partial plane sums
__device__ float g_gW1[Lq * Cc * Rr];       // gain[c]*W1[l,c,r]
__device__ float g_W2 [Lq * Rr * Kk];       // W2[l,r,k]

// ============================================================
// Kernel 1: partial sums of x planes. grid = 2048 (4 seg/plane),
// 256 threads, MLP=4 batched float4 loads.
// ============================================================
__global__ void mean_kernel(const float* __restrict__ x)
{
    const int bid   = blockIdx.x;
    const int plane = bid >> 2;
    const int seg   = bid & 3;
    const float4* __restrict__ p =
        (const float4*)(x + (size_t)plane * HW + (size_t)seg * SEG);
    const int n4 = SEG / 4;                       // 7200

    float s0 = 0.f, s1 = 0.f, s2 = 0.f, s3 = 0.f;
    int i = threadIdx.x;
    for (; i + 768 < n4; i += 1024) {
        float4 a = p[i];
        float4 b = p[i + 256];
        float4 c = p[i + 512];
        float4 d = p[i + 768];
        s0 += (a.x + a.y) + (a.z + a.w);
        s1 += (b.x + b.y) + (b.z + b.w);
        s2 += (c.x + c.y) + (c.z + c.w);
        s3 += (d.x + d.y) + (d.z + d.w);
    }
    for (; i < n4; i += 256) {
        float4 a = p[i];
        s0 += (a.x + a.y) + (a.z + a.w);
    }
    float s = (s0 + s1) + (s2 + s3);

    #pragma unroll
    for (int o = 16; o > 0; o >>= 1)
        s += __shfl_xor_sync(0xffffffffu, s, o);

    __shared__ float ws[8];
    const int lane = threadIdx.x & 31, wid = threadIdx.x >> 5;
    if (lane == 0) ws[wid] = s;
    __syncthreads();
    if (wid == 0) {
        s = (lane < 8) ? ws[lane] : 0.f;
        #pragma unroll
        for (int o = 4; o > 0; o >>= 1)
            s += __shfl_xor_sync(0xffffffffu, s, o);
        if (lane == 0)
            g_part[bid] = s;
    }
}

// ============================================================
// Kernel 2: fused hypernet. 41 blocks x 128 threads.
// Every block redundantly computes ctx reduce + layer 1
// (small: 2KB g_part + 32KB Wa, L2-hit after wave 1), then
// its own 128-output slice of layer 2.
// ============================================================
__global__ void __launch_bounds__(128)
hyper_kernel(const float* __restrict__ Wa,
             const float* __restrict__ ba,
             const float* __restrict__ Wb,
             const float* __restrict__ bb,
             const float* __restrict__ gain)
{
    __shared__ float ctxs[Lq * Cc];    // 512
    __shared__ float hs[Lq * Ch];      // 256

    const int tid = threadIdx.x;

    // ctx reduce: 512 values, 4 per thread
    #pragma unroll
    for (int o = 0; o < 4; o++) {
        const int idx = tid + 128 * o;
        const float* gp = &g_part[idx * 4];
        ctxs[idx] = ((gp[0] + gp[1]) + (gp[2] + gp[3])) * (1.0f / (float)HW);
    }
    __syncthreads();

    // layer 1: 256 outputs, 2 per thread
    #pragma unroll
    for (int o = 0; o < 2; o++) {
        const int idx = tid + 128 * o;
        const int l = idx >> 6;
        const int j = idx & 63;
        float acc = ba[j];
        const float* c = &ctxs[l * Cc];
        #pragma unroll 8
        for (int i = 0; i < Cc; i++)
            acc = fmaf(c[i], Wa[i * Ch + j], acc);
        hs[idx] = acc / (1.0f + expf(-acc));
    }
    __syncthreads();

    // layer 2: this block's 128-output slice
    const int idx = blockIdx.x * 128 + tid;
    const int l   = idx / WFN;
    const int col = idx - l * WFN;

    float acc = bb[col];
    const float* h = &hs[l * Ch];
    #pragma unroll 8
    for (int j = 0; j < Ch; j++)
        acc = fmaf(h[j], Wb[j * WFN + col], acc);

    if (col < Cc * Rr) {
        const int c = col >> 3;
        g_gW1[l * (Cc * Rr) + col] = gain[c] * acc;
    } else {
        g_W2[l * (Rr * Kk) + (col - Cc * Rr)] = acc;
    }
}

// ============================================================
// Kernel 3: fused  z = W2 @ Y + out = x + gW1 @ z  (R6 proven)
// grid = (225, 4), 128 threads, 4 px/thread, float4 throughout.
// ============================================================
__global__ void __launch_bounds__(128)
bias_kernel(const float* __restrict__ x,
            const float* __restrict__ Y,
            float*       __restrict__ out)
{
    const int l  = blockIdx.y;
    const int p0 = (blockIdx.x * 128 + threadIdx.x) * 4;

    __shared__ float sW2[Rr * Kk];
    __shared__ float sW1[Cc * Rr];

    for (int i = threadIdx.x; i < Rr * Kk; i += 128) sW2[i] = g_W2[l * Rr * Kk + i];
    for (int i = threadIdx.x; i < Cc * Rr; i += 128) sW1[i] = g_gW1[l * Cc * Rr + i];
    __syncthreads();

    float4 z[Rr];
    #pragma unroll
    for (int r = 0; r < Rr; r++) z[r] = make_float4(0.f, 0.f, 0.f, 0.f);

    #pragma unroll
    for (int k = 0; k < Kk; k++) {
        const float4 y = *(const float4*)(Y + (size_t)k * HW + p0);
        #pragma unroll
        for (int r = 0; r < Rr; r++) {
            const float w = sW2[r * Kk + k];
            z[r].x = fmaf(w, y.x, z[r].x);
            z[r].y = fmaf(w, y.y, z[r].y);
            z[r].z = fmaf(w, y.z, z[r].z);
            z[r].w = fmaf(w, y.w, z[r].w);
        }
    }

    const float* xb = x   + (size_t)l * Cc * HW + p0;
    float*       ob = out + (size_t)l * Cc * HW + p0;

    #pragma unroll 4
    for (int c = 0; c < Cc; c++) {
        float4 v = *(const float4*)(xb + (size_t)c * HW);
        const float4 wa = *(const float4*)&sW1[c * Rr];
        const float4 wb = *(const float4*)&sW1[c * Rr + 4];

        v.x = fmaf(wa.x, z[0].x, v.x); v.y = fmaf(wa.x, z[0].y, v.y);
        v.z = fmaf(wa.x, z[0].z, v.z); v.w = fmaf(wa.x, z[0].w, v.w);
        v.x = fmaf(wa.y, z[1].x, v.x); v.y = fmaf(wa.y, z[1].y, v.y);
        v.z = fmaf(wa.y, z[1].z, v.z); v.w = fmaf(wa.y, z[1].w, v.w);
        v.x = fmaf(wa.z, z[2].x, v.x); v.y = fmaf(wa.z, z[2].y, v.y);
        v.z = fmaf(wa.z, z[2].z, v.z); v.w = fmaf(wa.z, z[2].w, v.w);
        v.x = fmaf(wa.w, z[3].x, v.x); v.y = fmaf(wa.w, z[3].y, v.y);
        v.z = fmaf(wa.w, z[3].z, v.z); v.w = fmaf(wa.w, z[3].w, v.w);
        v.x = fmaf(wb.x, z[4].x, v.x); v.y = fmaf(wb.x, z[4].y, v.y);
        v.z = fmaf(wb.x, z[4].z, v.z); v.w = fmaf(wb.x, z[4].w, v.w);
        v.x = fmaf(wb.y, z[5].x, v.x); v.y = fmaf(wb.y, z[5].y, v.y);
        v.z = fmaf(wb.y, z[5].z, v.z); v.w = fmaf(wb.y, z[5].w, v.w);
        v.x = fmaf(wb.z, z[6].x, v.x); v.y = fmaf(wb.z, z[6].y, v.y);
        v.z = fmaf(wb.z, z[6].z, v.z); v.w = fmaf(wb.z, z[6].w, v.w);
        v.x = fmaf(wb.w, z[7].x, v.x); v.y = fmaf(wb.w, z[7].y, v.y);
        v.z = fmaf(wb.w, z[7].z, v.z); v.w = fmaf(wb.w, z[7].w, v.w);

        *(float4*)(ob + (size_t)c * HW) = v;
    }
}

// ============================================================
extern "C" void kernel_launch(void* const* d_in, const int* in_sizes, int n_in,
                              void* d_out, int out_size)
{
    const float* x    = (const float*)d_in[0];
    const float* Wa   = (const float*)d_in[1];
    const float* ba   = (const float*)d_in[2];
    const float* Wb   = (const float*)d_in[3];
    const float* bb   = (const float*)d_in[4];
    const float* gain = (const float*)d_in[5];
    const float* Y    = (const float*)d_in[6];
    float* out        = (float*)d_out;

    mean_kernel<<<Lq * Cc * 4, 256>>>(x);
    hyper_kernel<<<41, 128>>>(Wa, ba, Wb, bb, gain);
    bias_kernel<<<dim3(225, Lq), 128>>>(x, Y, out);
}